// round 14
// baseline (speedup 1.0000x reference)
#include <cuda_runtime.h>
#include <cuda_fp16.h>
#include <math_constants.h>
#include <cstdint>

#define NTOK 4096
#define DMODEL 1024
#define NH 16
#define HD 64
#define QSCALE (0.125f * 1.4426950408889634f)
#define ONES2 0x3C003C00u

// ---------------- device scratch (allocation-free rule) ----------------
__device__ __half   g_qh[NTOK * DMODEL];
__device__ __half   g_kh[NTOK * DMODEL];
__device__ __half   g_vh[NTOK * DMODEL];
__device__ __half   g_Wt[4 * DMODEL * DMODEL];   // W^T, [z][n][k] fp16
__device__ __half   g_Qh[NH * NTOK * HD];
__device__ __half   g_Kh[NH * NTOK * HD];
__device__ __half   g_Vt[NH * HD * NTOK];
__device__ __half   g_Hh[NTOK * DMODEL];

// ---------------- helpers ----------------
__device__ __forceinline__ uint32_t packh2(float x, float y) {
    __half2 h = __floats2half2_rn(x, y);
    return *(uint32_t*)&h;
}
__device__ __forceinline__ float ex2f(float x) {
    float r;
    asm("ex2.approx.ftz.f32 %0, %1;" : "=f"(r) : "f"(x));
    return r;
}
__device__ __forceinline__ uint32_t exp2_h2(float t_lo, float t_hi) {
    uint32_t w, r;
    asm("cvt.rn.f16x2.f32 %0, %1, %2;" : "=r"(w) : "f"(t_hi), "f"(t_lo));
    asm("ex2.approx.f16x2 %0, %1;" : "=r"(r) : "r"(w));
    return r;
}
__device__ __forceinline__ uint32_t smem_u32(const void* p) {
    uint32_t a;
    asm("{ .reg .u64 t; cvta.to.shared.u64 t, %1; cvt.u32.u64 %0, t; }"
        : "=r"(a) : "l"(p));
    return a;
}
__device__ __forceinline__ void cpa16(uint32_t dst, const void* src) {
    asm volatile("cp.async.cg.shared.global [%0], [%1], 16;"
                 :: "r"(dst), "l"(src) : "memory");
}
#define CP_COMMIT() asm volatile("cp.async.commit_group;" ::: "memory")
#define CP_WAIT1()  asm volatile("cp.async.wait_group 1;" ::: "memory")

#define LDSM4(r0, r1, r2, r3, addr) \
    asm volatile("ldmatrix.sync.aligned.m8n8.x4.shared.b16 {%0,%1,%2,%3}, [%4];" \
        : "=r"(r0), "=r"(r1), "=r"(r2), "=r"(r3) : "r"(addr))

__device__ __forceinline__ void mma16(float c[4], const uint32_t a[4],
                                      uint32_t b0, uint32_t b1) {
    asm volatile(
        "mma.sync.aligned.m16n8k16.row.col.f32.f16.f16.f32 "
        "{%0,%1,%2,%3},{%4,%5,%6,%7},{%8,%9},{%0,%1,%2,%3};"
        : "+f"(c[0]), "+f"(c[1]), "+f"(c[2]), "+f"(c[3])
        : "r"(a[0]), "r"(a[1]), "r"(a[2]), "r"(a[3]), "r"(b0), "r"(b1));
}

// ============================================================================
// Conversion kernels (unchanged)
// ============================================================================
__global__ __launch_bounds__(256)
void cvt_act(const float* __restrict__ q, const float* __restrict__ k,
             const float* __restrict__ v) {
    const int z = blockIdx.z;
    const float* src = (z == 0) ? q : (z == 1) ? k : v;
    __half* dst = (z == 0) ? g_qh : (z == 1) ? g_kh : g_vh;
    size_t i = ((size_t)blockIdx.x * 256 + threadIdx.x) * 8;
    float4 a = *(const float4*)(src + i);
    float4 b = *(const float4*)(src + i + 4);
    uint4 o = {packh2(a.x, a.y), packh2(a.z, a.w),
               packh2(b.x, b.y), packh2(b.z, b.w)};
    *(uint4*)(dst + i) = o;
}

__global__ __launch_bounds__(256)
void cvt_wgt_t(const float* __restrict__ Wq, const float* __restrict__ Wk,
               const float* __restrict__ Wv, const float* __restrict__ Wo) {
    const int z = blockIdx.z;
    const float* W = (z == 0) ? Wq : (z == 1) ? Wk : (z == 2) ? Wv : Wo;
    __half* dst = g_Wt + (size_t)z * DMODEL * DMODEL;
    __shared__ __half sm[32][33];
    const int k0 = blockIdx.x * 32, n0 = blockIdx.y * 32;
    const int tx = threadIdx.x & 31, ty = threadIdx.x >> 5;
#pragma unroll
    for (int i = 0; i < 4; i++) {
        int kk = ty * 4 + i;
        sm[tx][kk] = __float2half(W[(size_t)(k0 + kk) * DMODEL + n0 + tx]);
    }
    __syncthreads();
#pragma unroll
    for (int i = 0; i < 4; i++) {
        int n = ty * 4 + i;
        dst[(size_t)(n0 + n) * DMODEL + k0 + tx] = sm[n][tx];
    }
}

// ============================================================================
// GEMM v4 (unchanged from r13): BK=64, 3-stage cp.async ring, dual ldmatrix.
// ============================================================================
#define GROW 144
#define GT_B (128 * GROW)
#define GST (2 * GT_B)
#define G_SMEM (3 * GST)

__global__ __launch_bounds__(256, 2)
void gemm_fp16(const __half* __restrict__ A0, const __half* __restrict__ B0,
               float* __restrict__ Cout, int fused) {
    extern __shared__ char smc[];
    const uint32_t sb = smem_u32(smc);
    const int tid = threadIdx.x, lane = tid & 31, wid = tid >> 5;
    const int wm = wid >> 2, wn = wid & 3;
    const int g = lane >> 2, lq = lane & 3;
    const int bm = blockIdx.y * 128, bn = blockIdx.x * 128;

    const __half* A;
    const __half* Bt;
    int mode;
    if (fused) {
        int z = blockIdx.z;
        A = (z == 0) ? g_qh : (z == 1) ? g_kh : g_vh;
        Bt = g_Wt + (size_t)z * DMODEL * DMODEL;
        mode = z + 1;
    } else {
        A = A0; Bt = B0; mode = 0;
    }

    float acc[4][4][4];
#pragma unroll
    for (int i = 0; i < 4; i++)
#pragma unroll
        for (int j = 0; j < 4; j++)
#pragma unroll
            for (int r = 0; r < 4; r++) acc[i][j][r] = 0.f;

    auto issue = [&](int buf, int c) {
        uint32_t ab = sb + (uint32_t)buf * GST;
        uint32_t bb = ab + GT_B;
#pragma unroll
        for (int t = 0; t < 4; t++) {
            int idx = t * 256 + tid;
            int row = idx >> 3, ch = idx & 7;
            cpa16(ab + row * GROW + ch * 16,
                  A + (size_t)(bm + row) * DMODEL + c * 64 + ch * 8);
            cpa16(bb + row * GROW + ch * 16,
                  Bt + (size_t)(bn + row) * DMODEL + c * 64 + ch * 8);
        }
    };
    issue(0, 0); CP_COMMIT();
    issue(1, 1); CP_COMMIT();

    const int mat = lane >> 3, rr = lane & 7;
    const uint32_t aoff = (uint32_t)((wm * 64 + (mat & 1) * 8 + rr) * GROW) +
                          (uint32_t)(lane >> 4) * 16;
    const uint32_t boff0 = (uint32_t)((wn * 32 + (mat >> 1) * 8 + rr) * GROW) +
                           (uint32_t)(mat & 1) * 16;
    const uint32_t boff1 = boff0 + 16 * GROW;

    auto chunk = [&](int c, int buf, int nbuf) {
        CP_WAIT1();
        __syncthreads();
        if (c + 2 < 16) issue(nbuf, c + 2);
        CP_COMMIT();
        uint32_t ab = sb + (uint32_t)buf * GST;
        uint32_t bb = ab + GT_B;
#pragma unroll
        for (int ks = 0; ks < 4; ks++) {
            uint32_t b0, b1, b2, b3, b4, b5, b6, b7;
            LDSM4(b0, b1, b2, b3, bb + boff0 + ks * 32);
            LDSM4(b4, b5, b6, b7, bb + boff1 + ks * 32);
#pragma unroll
            for (int mt = 0; mt < 4; mt++) {
                uint32_t a[4];
                LDSM4(a[0], a[1], a[2], a[3],
                      ab + aoff + (uint32_t)mt * 16 * GROW + ks * 32);
                mma16(acc[mt][0], a, b0, b1);
                mma16(acc[mt][1], a, b2, b3);
                mma16(acc[mt][2], a, b4, b5);
                mma16(acc[mt][3], a, b6, b7);
            }
        }
        __syncthreads();
    };

    for (int t = 0; t < 5; t++) {
        chunk(3 * t + 0, 0, 2);
        chunk(3 * t + 1, 1, 0);
        chunk(3 * t + 2, 2, 1);
    }
    chunk(15, 0, 2);

#pragma unroll
    for (int mt = 0; mt < 4; mt++) {
#pragma unroll
        for (int nt = 0; nt < 4; nt++) {
            int r0 = bm + wm * 64 + mt * 16 + g;
            int cc = bn + wn * 32 + nt * 8 + 2 * lq;
            if (mode == 0) {
                *(float2*)(Cout + (size_t)r0 * DMODEL + cc) =
                    make_float2(acc[mt][nt][0], acc[mt][nt][1]);
                *(float2*)(Cout + (size_t)(r0 + 8) * DMODEL + cc) =
                    make_float2(acc[mt][nt][2], acc[mt][nt][3]);
            } else if (mode == 1 || mode == 2) {
                __half* C = (mode == 1) ? g_Qh : g_Kh;
                const float sc = (mode == 1) ? QSCALE : 1.f;
                int h = cc >> 6, d = cc & 63;
                *(uint32_t*)(C + (size_t)h * (NTOK * HD) + (size_t)r0 * HD + d) =
                    packh2(acc[mt][nt][0] * sc, acc[mt][nt][1] * sc);
                *(uint32_t*)(C + (size_t)h * (NTOK * HD) + (size_t)(r0 + 8) * HD + d) =
                    packh2(acc[mt][nt][2] * sc, acc[mt][nt][3] * sc);
            } else {
                int h = cc >> 6, d = cc & 63;
                size_t base = (size_t)h * (HD * NTOK);
                g_Vt[base + (size_t)d * NTOK + r0]           = __float2half(acc[mt][nt][0]);
                g_Vt[base + (size_t)(d + 1) * NTOK + r0]     = __float2half(acc[mt][nt][1]);
                g_Vt[base + (size_t)d * NTOK + r0 + 8]       = __float2half(acc[mt][nt][2]);
                g_Vt[base + (size_t)(d + 1) * NTOK + r0 + 8] = __float2half(acc[mt][nt][3]);
            }
        }
    }
}

// ============================================================================
// Flash v11: BQ=128, 512 threads (16 warps = 8 wm x 2 wn). Per-warp math is
// byte-identical to the proven r11 kernel; staging/barriers amortized over 2x
// the q-rows. 1 CTA/SM (RF-exact), same warps/SM as before.
// ============================================================================
#define FSQ 72
#define FROWB (FSQ * 2)                    // 144 B
#define TILEB (64 * FROWB)                 // 9216 B per K or V tile
#define QTILEB (128 * FROWB)               // 18432 B
#define FH_SMEM (QTILEB + 3 * 2 * TILEB)   // 73728 B

__global__ __launch_bounds__(512, 1)
void flash_h8() {
    extern __shared__ char smc[];
    __half* Qs = (__half*)smc;
    const uint32_t sb = smem_u32(smc);
    float* obuf = (float*)smc;             // epilogue alias (128 x 66 f32)

    const int qt = blockIdx.x, h = blockIdx.y;
    const int tid = threadIdx.x;
    const int wid = tid >> 5, lane = tid & 31;
    const int wm = wid & 7, wn = wid >> 3;
    const int g = lane >> 2, lq = lane & 3;
    const int m0 = wm * 16;
    const int mat = lane >> 3, rr = lane & 7;

    const __half* Qh  = g_Qh + (size_t)h * (NTOK * HD) + (size_t)qt * 128 * HD;
    const __half* Kh  = g_Kh + (size_t)h * (NTOK * HD);
    const __half* Vth = g_Vt + (size_t)h * (HD * NTOK);

    // Stage Q tile: 128 rows
#pragma unroll
    for (int t = 0; t < 2; t++) {
        int idx = t * 512 + tid;
        int row = idx >> 3, ch = idx & 7;
        *(uint4*)(Qs + row * FSQ + ch * 8) =
            *(const uint4*)(Qh + (size_t)row * HD + ch * 8);
    }

    auto issue_kv = [&](uint32_t kb, int s) {
        uint32_t vb = kb + TILEB;
        int r = tid >> 3, ch = tid & 7;    // 512 threads cover 64x8 chunks
        cpa16(kb + r * FROWB + ch * 16,
              Kh + (size_t)(s * 64 + r) * HD + ch * 8);
        cpa16(vb + r * FROWB + ch * 16,
              Vth + (size_t)r * NTOK + s * 64 + ch * 8);
    };
    issue_kv(sb + QTILEB, 0); CP_COMMIT();
    issue_kv(sb + QTILEB + 2 * TILEB, 1); CP_COMMIT();
    __syncthreads();

    // Hoist Q fragments
    uint32_t qa[4][4];
#pragma unroll
    for (int ks = 0; ks < 4; ks++) {
        qa[ks][0] = *(const uint32_t*)(Qs + (m0 + g) * FSQ + ks * 16 + 2 * lq);
        qa[ks][1] = *(const uint32_t*)(Qs + (m0 + g + 8) * FSQ + ks * 16 + 2 * lq);
        qa[ks][2] = *(const uint32_t*)(Qs + (m0 + g) * FSQ + ks * 16 + 2 * lq + 8);
        qa[ks][3] = *(const uint32_t*)(Qs + (m0 + g + 8) * FSQ + ks * 16 + 2 * lq + 8);
    }

    const uint32_t koff0 =
        (uint32_t)((wn * 32 + (mat >> 1) * 8 + rr) * FSQ + (mat & 1) * 8) * 2;
    const uint32_t koff1 = koff0 + 16 * FSQ * 2;
    uint32_t voff[4];
#pragma unroll
    for (int j = 0; j < 4; j++)
        voff[j] = (uint32_t)(((2 * j + (mat >> 1)) * 8 + rr) * FSQ +
                             wn * 32 + (mat & 1) * 8) * 2;

    float ofr[8][4];
#pragma unroll
    for (int nt = 0; nt < 8; nt++)
#pragma unroll
        for (int r = 0; r < 4; r++) ofr[nt][r] = 0.f;
    float lfr[4] = {0.f, 0.f, 0.f, 0.f};
    float mr0 = -CUDART_INF_F, mr1 = -CUDART_INF_F;

    auto body = [&](int s, int buf, int nbuf) {
        const uint32_t kb = sb + QTILEB + (uint32_t)buf * (2 * TILEB);
        const uint32_t vb = kb + TILEB;

        CP_WAIT1();
        __syncthreads();
        if (s + 2 < NTOK / 64)
            issue_kv(sb + QTILEB + (uint32_t)nbuf * (2 * TILEB), s + 2);
        CP_COMMIT();

        // --- S = Q K^T ---
        float sfr[4][4];
#pragma unroll
        for (int nt = 0; nt < 4; nt++)
#pragma unroll
            for (int r = 0; r < 4; r++) sfr[nt][r] = 0.f;
#pragma unroll
        for (int ks = 0; ks < 4; ks++) {
            uint32_t b0, b1, b2, b3;
            LDSM4(b0, b1, b2, b3, kb + koff0 + ks * 32);
            mma16(sfr[0], qa[ks], b0, b1);
            mma16(sfr[1], qa[ks], b2, b3);
            LDSM4(b0, b1, b2, b3, kb + koff1 + ks * 32);
            mma16(sfr[2], qa[ks], b0, b1);
            mma16(sfr[3], qa[ks], b2, b3);
        }

        // --- row max: packed f16x2, 2 shfl ---
        float pm0 = -CUDART_INF_F, pm1 = -CUDART_INF_F;
#pragma unroll
        for (int nt = 0; nt < 4; nt++) {
            pm0 = fmaxf(pm0, fmaxf(sfr[nt][0], sfr[nt][1]));
            pm1 = fmaxf(pm1, fmaxf(sfr[nt][2], sfr[nt][3]));
        }
        uint32_t pw;
        asm("cvt.rn.f16x2.f32 %0, %1, %2;" : "=r"(pw) : "f"(pm1), "f"(pm0));
        uint32_t o1 = __shfl_xor_sync(0xffffffffu, pw, 1);
        asm("max.f16x2 %0, %1, %2;" : "=r"(pw) : "r"(pw), "r"(o1));
        uint32_t o2 = __shfl_xor_sync(0xffffffffu, pw, 2);
        asm("max.f16x2 %0, %1, %2;" : "=r"(pw) : "r"(pw), "r"(o2));
        __half2 hp = *(__half2*)&pw;
        float mn0 = fmaxf(mr0, __low2float(hp));
        float mn1 = fmaxf(mr1, __high2float(hp));
        bool upd = (mn0 > mr0) || (mn1 > mr1);

        // --- exp2 in f16x2; P = f16 A-frags ---
        uint32_t p[4][2];
#pragma unroll
        for (int nt = 0; nt < 4; nt++) {
            p[nt][0] = exp2_h2(sfr[nt][0] - mn0, sfr[nt][1] - mn0);
            p[nt][1] = exp2_h2(sfr[nt][2] - mn1, sfr[nt][3] - mn1);
        }

        float al0 = ex2f(mr0 - mn0);
        float al1 = ex2f(mr1 - mn1);
        mr0 = mn0; mr1 = mn1;
        if (upd) {
#pragma unroll
            for (int nt = 0; nt < 8; nt++) {
                ofr[nt][0] *= al0; ofr[nt][1] *= al0;
                ofr[nt][2] *= al1; ofr[nt][3] *= al1;
            }
            lfr[0] *= al0; lfr[1] *= al0;
            lfr[2] *= al1; lfr[3] *= al1;
        }

        // --- O += P V ; l += P·1 ---
#pragma unroll
        for (int kc = 0; kc < 2; kc++) {
            uint32_t pa[4] = {p[2 * kc][0], p[2 * kc][1],
                              p[2 * kc + 1][0], p[2 * kc + 1][1]};
#pragma unroll
            for (int j = 0; j < 4; j++) {
                uint32_t b0, b1, b2, b3;
                LDSM4(b0, b1, b2, b3, vb + voff[j] + kc * 32);
                mma16(ofr[2 * j],     pa, b0, b1);
                mma16(ofr[2 * j + 1], pa, b2, b3);
            }
            mma16(lfr, pa, ONES2, ONES2);
        }
    };

    for (int t3 = 0; t3 < 63; t3 += 3) {
        body(t3 + 0, 0, 2);
        body(t3 + 1, 1, 0);
        body(t3 + 2, 2, 1);
    }
    body(63, 0, 2);

    float lr0 = lfr[0], lr1 = lfr[2];

    // ---- Epilogue: merge wn halves; write fp16 H ----
    __syncthreads();
    if (wn == 1) {
#pragma unroll
        for (int nt = 0; nt < 8; nt++) {
            *(float2*)(obuf + (m0 + g) * 66 + nt * 8 + 2 * lq) =
                make_float2(ofr[nt][0], ofr[nt][1]);
            *(float2*)(obuf + (m0 + 8 + g) * 66 + nt * 8 + 2 * lq) =
                make_float2(ofr[nt][2], ofr[nt][3]);
        }
        if (lq == 0) {
            *(float2*)(obuf + (m0 + g) * 66 + 64) = make_float2(mr0, lr0);
            *(float2*)(obuf + (m0 + 8 + g) * 66 + 64) = make_float2(mr1, lr1);
        }
    }
    __syncthreads();
    if (wn == 0) {
        float2 ml0 = *(const float2*)(obuf + (m0 + g) * 66 + 64);
        float2 ml1 = *(const float2*)(obuf + (m0 + 8 + g) * 66 + 64);
        float M0 = fmaxf(mr0, ml0.x);
        float M1 = fmaxf(mr1, ml1.x);
        float e00 = ex2f(mr0 - M0), e01 = ex2f(ml0.x - M0);
        float e10 = ex2f(mr1 - M1), e11 = ex2f(ml1.x - M1);
        float il0 = 1.f / (lr0 * e00 + ml0.y * e01);
        float il1 = 1.f / (lr1 * e10 + ml1.y * e11);
        int n0g = qt * 128 + m0 + g;
#pragma unroll
        for (int nt = 0; nt < 8; nt++) {
            float2 oa = *(const float2*)(obuf + (m0 + g) * 66 + nt * 8 + 2 * lq);
            float2 ob = *(const float2*)(obuf + (m0 + 8 + g) * 66 + nt * 8 + 2 * lq);
            int col = h * HD + nt * 8 + 2 * lq;
            *(uint32_t*)(g_Hh + (size_t)n0g * DMODEL + col) =
                packh2((ofr[nt][0] * e00 + oa.x * e01) * il0,
                       (ofr[nt][1] * e00 + oa.y * e01) * il0);
            *(uint32_t*)(g_Hh + (size_t)(n0g + 8) * DMODEL + col) =
                packh2((ofr[nt][2] * e10 + ob.x * e11) * il1,
                       (ofr[nt][3] * e10 + ob.y * e11) * il1);
        }
    }
}

// ---------------------------------------------------------------------------
extern "C" void kernel_launch(void* const* d_in, const int* in_sizes, int n_in,
                              void* d_out, int out_size) {
    const float* q  = (const float*)d_in[0];
    const float* k  = (const float*)d_in[1];
    const float* v  = (const float*)d_in[2];
    const float* Wq = (const float*)d_in[3];
    const float* Wk = (const float*)d_in[4];
    const float* Wv = (const float*)d_in[5];
    const float* Wo = (const float*)d_in[6];

    __half *Hp, *Wtp;
    cudaGetSymbolAddress((void**)&Hp, g_Hh);
    cudaGetSymbolAddress((void**)&Wtp, g_Wt);

    cudaFuncSetAttribute(gemm_fp16, cudaFuncAttributeMaxDynamicSharedMemorySize, G_SMEM);
    cudaFuncSetAttribute(flash_h8, cudaFuncAttributeMaxDynamicSharedMemorySize, FH_SMEM);

    cvt_act<<<dim3(2048, 1, 3), 256>>>(q, k, v);
    cvt_wgt_t<<<dim3(32, 32, 4), 256>>>(Wq, Wk, Wv, Wo);

    gemm_fp16<<<dim3(8, 32, 3), 256, G_SMEM>>>(nullptr, nullptr, nullptr, 1);

    flash_h8<<<dim3(NTOK / 128, NH), 512, FH_SMEM>>>();

    gemm_fp16<<<dim3(8, 32, 1), 256, G_SMEM>>>(
        Hp, Wtp + (size_t)3 * DMODEL * DMODEL, (float*)d_out, 0);
}

// round 16
// speedup vs baseline: 1.0592x; 1.0592x over previous
#include <cuda_runtime.h>
#include <cuda_fp16.h>
#include <math_constants.h>
#include <cstdint>

#define NTOK 4096
#define DMODEL 1024
#define NH 16
#define HD 64
#define QSCALE (0.125f * 1.4426950408889634f)
#define ONES2 0x3C003C00u

// ---------------- device scratch (allocation-free rule) ----------------
__device__ __half   g_qh[NTOK * DMODEL];
__device__ __half   g_kh[NTOK * DMODEL];
__device__ __half   g_vh[NTOK * DMODEL];
__device__ __half   g_Wh[4 * DMODEL * DMODEL];   // weights fp16, natural [k][n]
__device__ __half   g_Qh[NH * NTOK * HD];
__device__ __half   g_Kh[NH * NTOK * HD];
__device__ __half   g_Vt[NH * HD * NTOK];
__device__ __half   g_Hh[NTOK * DMODEL];

// ---------------- helpers ----------------
__device__ __forceinline__ uint32_t packh2(float x, float y) {
    __half2 h = __floats2half2_rn(x, y);
    return *(uint32_t*)&h;
}
__device__ __forceinline__ float ex2f(float x) {
    float r;
    asm("ex2.approx.ftz.f32 %0, %1;" : "=f"(r) : "f"(x));
    return r;
}
__device__ __forceinline__ uint32_t exp2_h2(float t_lo, float t_hi) {
    uint32_t w, r;
    asm("cvt.rn.f16x2.f32 %0, %1, %2;" : "=r"(w) : "f"(t_hi), "f"(t_lo));
    asm("ex2.approx.f16x2 %0, %1;" : "=r"(r) : "r"(w));
    return r;
}
__device__ __forceinline__ uint32_t smem_u32(const void* p) {
    uint32_t a;
    asm("{ .reg .u64 t; cvta.to.shared.u64 t, %1; cvt.u32.u64 %0, t; }"
        : "=r"(a) : "l"(p));
    return a;
}
__device__ __forceinline__ void cpa16(uint32_t dst, const void* src) {
    asm volatile("cp.async.cg.shared.global [%0], [%1], 16;"
                 :: "r"(dst), "l"(src) : "memory");
}
#define CP_COMMIT() asm volatile("cp.async.commit_group;" ::: "memory")
#define CP_WAIT1()  asm volatile("cp.async.wait_group 1;" ::: "memory")

#define LDSM4(r0, r1, r2, r3, addr) \
    asm volatile("ldmatrix.sync.aligned.m8n8.x4.shared.b16 {%0,%1,%2,%3}, [%4];" \
        : "=r"(r0), "=r"(r1), "=r"(r2), "=r"(r3) : "r"(addr))

#define LDSM4T(r0, r1, r2, r3, addr) \
    asm volatile("ldmatrix.sync.aligned.m8n8.x4.trans.shared.b16 {%0,%1,%2,%3}, [%4];" \
        : "=r"(r0), "=r"(r1), "=r"(r2), "=r"(r3) : "r"(addr))

__device__ __forceinline__ void mma16(float c[4], const uint32_t a[4],
                                      uint32_t b0, uint32_t b1) {
    asm volatile(
        "mma.sync.aligned.m16n8k16.row.col.f32.f16.f16.f32 "
        "{%0,%1,%2,%3},{%4,%5,%6,%7},{%8,%9},{%0,%1,%2,%3};"
        : "+f"(c[0]), "+f"(c[1]), "+f"(c[2]), "+f"(c[3])
        : "r"(a[0]), "r"(a[1]), "r"(a[2]), "r"(a[3]), "r"(b0), "r"(b1));
}

// ============================================================================
// Single conversion kernel: streaming vectorized f32->f16 for all 7 tensors.
// z: 0=q 1=k 2=v (4M elems) | 3=Wq 4=Wk 5=Wv 6=Wo (1M elems, bounds-guarded).
// ============================================================================
__global__ __launch_bounds__(256)
void cvt_all(const float* __restrict__ q, const float* __restrict__ k,
             const float* __restrict__ v, const float* __restrict__ Wq,
             const float* __restrict__ Wk, const float* __restrict__ Wv,
             const float* __restrict__ Wo) {
    const int z = blockIdx.z;
    const float* src;
    __half* dst;
    size_t limit;
    switch (z) {
        case 0: src = q;  dst = g_qh; limit = (size_t)NTOK * DMODEL; break;
        case 1: src = k;  dst = g_kh; limit = (size_t)NTOK * DMODEL; break;
        case 2: src = v;  dst = g_vh; limit = (size_t)NTOK * DMODEL; break;
        case 3: src = Wq; dst = g_Wh;                                  limit = (size_t)DMODEL * DMODEL; break;
        case 4: src = Wk; dst = g_Wh + (size_t)DMODEL * DMODEL;        limit = (size_t)DMODEL * DMODEL; break;
        case 5: src = Wv; dst = g_Wh + (size_t)2 * DMODEL * DMODEL;    limit = (size_t)DMODEL * DMODEL; break;
        default: src = Wo; dst = g_Wh + (size_t)3 * DMODEL * DMODEL;   limit = (size_t)DMODEL * DMODEL; break;
    }
    size_t i = ((size_t)blockIdx.x * 256 + threadIdx.x) * 8;
    if (i >= limit) return;
    float4 a = *(const float4*)(src + i);
    float4 b = *(const float4*)(src + i + 4);
    uint4 o = {packh2(a.x, a.y), packh2(a.z, a.w),
               packh2(b.x, b.y), packh2(b.z, b.w)};
    *(uint4*)(dst + i) = o;
}

// ============================================================================
// GEMM v5: A fp16 [m][k] (144 B rows), B fp16 natural [k][n] (64 k-rows x
// 272 B) with B-fragments via ldmatrix.x4.trans. BK=64, 3-stage cp.async
// ring. mma/LDSM counts identical to the proven v4.
// ============================================================================
#define GROW 144
#define GT_A (128 * GROW)                  // 18432
#define BROW 272
#define GT_BB (64 * BROW)                  // 17408
#define GST (GT_A + GT_BB)                 // 35840
#define G_SMEM (3 * GST)                   // 107520

__global__ __launch_bounds__(256, 2)
void gemm_fp16(const __half* __restrict__ A0, const __half* __restrict__ B0,
               float* __restrict__ Cout, int fused) {
    extern __shared__ char smc[];
    const uint32_t sb = smem_u32(smc);
    const int tid = threadIdx.x, lane = tid & 31, wid = tid >> 5;
    const int wm = wid >> 2, wn = wid & 3;
    const int g = lane >> 2, lq = lane & 3;
    const int bm = blockIdx.y * 128, bn = blockIdx.x * 128;

    const __half* A;
    const __half* Bk;   // [k][n]
    int mode;
    if (fused) {
        int z = blockIdx.z;
        A = (z == 0) ? g_qh : (z == 1) ? g_kh : g_vh;
        Bk = g_Wh + (size_t)z * DMODEL * DMODEL;
        mode = z + 1;
    } else {
        A = A0; Bk = B0; mode = 0;
    }

    float acc[4][4][4];
#pragma unroll
    for (int i = 0; i < 4; i++)
#pragma unroll
        for (int j = 0; j < 4; j++)
#pragma unroll
            for (int r = 0; r < 4; r++) acc[i][j][r] = 0.f;

    auto issue = [&](int buf, int c) {
        uint32_t ab = sb + (uint32_t)buf * GST;
        uint32_t bb = ab + GT_A;
        // A: 128 rows x 128 B (8 x 16B chunks)
#pragma unroll
        for (int t = 0; t < 4; t++) {
            int idx = t * 256 + tid;
            int row = idx >> 3, ch = idx & 7;
            cpa16(ab + row * GROW + ch * 16,
                  A + (size_t)(bm + row) * DMODEL + c * 64 + ch * 8);
        }
        // B: 64 k-rows x 256 B (16 x 16B chunks)
#pragma unroll
        for (int t = 0; t < 4; t++) {
            int idx = t * 256 + tid;
            int row = idx >> 4, ch = idx & 15;
            cpa16(bb + row * BROW + ch * 16,
                  Bk + (size_t)(c * 64 + row) * DMODEL + bn + ch * 8);
        }
    };
    issue(0, 0); CP_COMMIT();
    issue(1, 1); CP_COMMIT();

    const int mat = lane >> 3, rr = lane & 7;
    const uint32_t aoff = (uint32_t)((wm * 64 + (mat & 1) * 8 + rr) * GROW) +
                          (uint32_t)(lane >> 4) * 16;
    // B trans-frag base: k-local = (mat&1)*8 + rr ; n-local = wn*32 + (mat>>1)*8
    const uint32_t btb = (uint32_t)(((mat & 1) * 8 + rr) * BROW) +
                         (uint32_t)((wn * 32 + (mat >> 1) * 8) * 2);

    auto chunk = [&](int c, int buf, int nbuf) {
        CP_WAIT1();
        __syncthreads();
        if (c + 2 < 16) issue(nbuf, c + 2);
        CP_COMMIT();
        uint32_t ab = sb + (uint32_t)buf * GST;
        uint32_t bb = ab + GT_A;
#pragma unroll
        for (int ks = 0; ks < 4; ks++) {
            uint32_t b0, b1, b2, b3, b4, b5, b6, b7;
            LDSM4T(b0, b1, b2, b3, bb + btb + (uint32_t)ks * 16 * BROW);        // n 0..15
            LDSM4T(b4, b5, b6, b7, bb + btb + (uint32_t)ks * 16 * BROW + 32);   // n 16..31
#pragma unroll
            for (int mt = 0; mt < 4; mt++) {
                uint32_t a[4];
                LDSM4(a[0], a[1], a[2], a[3],
                      ab + aoff + (uint32_t)mt * 16 * GROW + ks * 32);
                mma16(acc[mt][0], a, b0, b1);
                mma16(acc[mt][1], a, b2, b3);
                mma16(acc[mt][2], a, b4, b5);
                mma16(acc[mt][3], a, b6, b7);
            }
        }
        __syncthreads();
    };

    for (int t = 0; t < 5; t++) {
        chunk(3 * t + 0, 0, 2);
        chunk(3 * t + 1, 1, 0);
        chunk(3 * t + 2, 2, 1);
    }
    chunk(15, 0, 2);

    // Epilogue
#pragma unroll
    for (int mt = 0; mt < 4; mt++) {
#pragma unroll
        for (int nt = 0; nt < 4; nt++) {
            int r0 = bm + wm * 64 + mt * 16 + g;
            int cc = bn + wn * 32 + nt * 8 + 2 * lq;
            if (mode == 0) {
                *(float2*)(Cout + (size_t)r0 * DMODEL + cc) =
                    make_float2(acc[mt][nt][0], acc[mt][nt][1]);
                *(float2*)(Cout + (size_t)(r0 + 8) * DMODEL + cc) =
                    make_float2(acc[mt][nt][2], acc[mt][nt][3]);
            } else if (mode == 1 || mode == 2) {
                __half* C = (mode == 1) ? g_Qh : g_Kh;
                const float sc = (mode == 1) ? QSCALE : 1.f;
                int h = cc >> 6, d = cc & 63;
                *(uint32_t*)(C + (size_t)h * (NTOK * HD) + (size_t)r0 * HD + d) =
                    packh2(acc[mt][nt][0] * sc, acc[mt][nt][1] * sc);
                *(uint32_t*)(C + (size_t)h * (NTOK * HD) + (size_t)(r0 + 8) * HD + d) =
                    packh2(acc[mt][nt][2] * sc, acc[mt][nt][3] * sc);
            } else {
                int h = cc >> 6, d = cc & 63;
                size_t base = (size_t)h * (HD * NTOK);
                g_Vt[base + (size_t)d * NTOK + r0]           = __float2half(acc[mt][nt][0]);
                g_Vt[base + (size_t)(d + 1) * NTOK + r0]     = __float2half(acc[mt][nt][1]);
                g_Vt[base + (size_t)d * NTOK + r0 + 8]       = __float2half(acc[mt][nt][2]);
                g_Vt[base + (size_t)(d + 1) * NTOK + r0 + 8] = __float2half(acc[mt][nt][3]);
            }
        }
    }
}

// ============================================================================
// Flash v9 (EXACT r13/r11 kernel — proven 228.0 us)
// ============================================================================
#define FSQ 72
#define FROWB (FSQ * 2)
#define TILEB (64 * FROWB)
#define FH_SMEM (TILEB + 3 * 2 * TILEB)    // 64512 B

__global__ __launch_bounds__(256, 2)
void flash_h6() {
    extern __shared__ char smc[];
    __half* Qs = (__half*)smc;
    const uint32_t sb = smem_u32(smc);
    float* obuf = (float*)smc;

    const int qt = blockIdx.x, h = blockIdx.y;
    const int tid = threadIdx.x;
    const int wid = tid >> 5, lane = tid & 31;
    const int wm = wid & 3, wn = wid >> 2;
    const int g = lane >> 2, lq = lane & 3;
    const int m0 = wm * 16;
    const int mat = lane >> 3, rr = lane & 7;

    const __half* Qh  = g_Qh + (size_t)h * (NTOK * HD) + (size_t)qt * 64 * HD;
    const __half* Kh  = g_Kh + (size_t)h * (NTOK * HD);
    const __half* Vth = g_Vt + (size_t)h * (HD * NTOK);

#pragma unroll
    for (int t = 0; t < 2; t++) {
        int idx = t * 256 + tid;
        int row = idx >> 3, ch = idx & 7;
        *(uint4*)(Qs + row * FSQ + ch * 8) =
            *(const uint4*)(Qh + (size_t)row * HD + ch * 8);
    }

    auto issue_kv = [&](uint32_t kb, int s) {
        uint32_t vb = kb + TILEB;
#pragma unroll
        for (int t = 0; t < 2; t++) {
            int idx = t * 256 + tid;
            int r = idx >> 3, ch = idx & 7;
            cpa16(kb + r * FROWB + ch * 16,
                  Kh + (size_t)(s * 64 + r) * HD + ch * 8);
            cpa16(vb + r * FROWB + ch * 16,
                  Vth + (size_t)r * NTOK + s * 64 + ch * 8);
        }
    };
    issue_kv(sb + TILEB, 0); CP_COMMIT();
    issue_kv(sb + TILEB + 2 * TILEB, 1); CP_COMMIT();
    __syncthreads();

    uint32_t qa[4][4];
#pragma unroll
    for (int ks = 0; ks < 4; ks++) {
        qa[ks][0] = *(const uint32_t*)(Qs + (m0 + g) * FSQ + ks * 16 + 2 * lq);
        qa[ks][1] = *(const uint32_t*)(Qs + (m0 + g + 8) * FSQ + ks * 16 + 2 * lq);
        qa[ks][2] = *(const uint32_t*)(Qs + (m0 + g) * FSQ + ks * 16 + 2 * lq + 8);
        qa[ks][3] = *(const uint32_t*)(Qs + (m0 + g + 8) * FSQ + ks * 16 + 2 * lq + 8);
    }

    const uint32_t koff0 =
        (uint32_t)((wn * 32 + (mat >> 1) * 8 + rr) * FSQ + (mat & 1) * 8) * 2;
    const uint32_t koff1 = koff0 + 16 * FSQ * 2;
    uint32_t voff[4];
#pragma unroll
    for (int j = 0; j < 4; j++)
        voff[j] = (uint32_t)(((2 * j + (mat >> 1)) * 8 + rr) * FSQ +
                             wn * 32 + (mat & 1) * 8) * 2;

    float ofr[8][4];
#pragma unroll
    for (int nt = 0; nt < 8; nt++)
#pragma unroll
        for (int r = 0; r < 4; r++) ofr[nt][r] = 0.f;
    float lfr[4] = {0.f, 0.f, 0.f, 0.f};
    float mr0 = -CUDART_INF_F, mr1 = -CUDART_INF_F;

    auto body = [&](int s, int buf, int nbuf) {
        const uint32_t kb = sb + TILEB + (uint32_t)buf * (2 * TILEB);
        const uint32_t vb = kb + TILEB;

        CP_WAIT1();
        __syncthreads();
        if (s + 2 < NTOK / 64)
            issue_kv(sb + TILEB + (uint32_t)nbuf * (2 * TILEB), s + 2);
        CP_COMMIT();

        float sfr[4][4];
#pragma unroll
        for (int nt = 0; nt < 4; nt++)
#pragma unroll
            for (int r = 0; r < 4; r++) sfr[nt][r] = 0.f;
#pragma unroll
        for (int ks = 0; ks < 4; ks++) {
            uint32_t b0, b1, b2, b3;
            LDSM4(b0, b1, b2, b3, kb + koff0 + ks * 32);
            mma16(sfr[0], qa[ks], b0, b1);
            mma16(sfr[1], qa[ks], b2, b3);
            LDSM4(b0, b1, b2, b3, kb + koff1 + ks * 32);
            mma16(sfr[2], qa[ks], b0, b1);
            mma16(sfr[3], qa[ks], b2, b3);
        }

        float pm0 = -CUDART_INF_F, pm1 = -CUDART_INF_F;
#pragma unroll
        for (int nt = 0; nt < 4; nt++) {
            pm0 = fmaxf(pm0, fmaxf(sfr[nt][0], sfr[nt][1]));
            pm1 = fmaxf(pm1, fmaxf(sfr[nt][2], sfr[nt][3]));
        }
        uint32_t pw;
        asm("cvt.rn.f16x2.f32 %0, %1, %2;" : "=r"(pw) : "f"(pm1), "f"(pm0));
        uint32_t o1 = __shfl_xor_sync(0xffffffffu, pw, 1);
        asm("max.f16x2 %0, %1, %2;" : "=r"(pw) : "r"(pw), "r"(o1));
        uint32_t o2 = __shfl_xor_sync(0xffffffffu, pw, 2);
        asm("max.f16x2 %0, %1, %2;" : "=r"(pw) : "r"(pw), "r"(o2));
        __half2 hp = *(__half2*)&pw;
        float mn0 = fmaxf(mr0, __low2float(hp));
        float mn1 = fmaxf(mr1, __high2float(hp));
        bool upd = (mn0 > mr0) || (mn1 > mr1);

        uint32_t p[4][2];
#pragma unroll
        for (int nt = 0; nt < 4; nt++) {
            p[nt][0] = exp2_h2(sfr[nt][0] - mn0, sfr[nt][1] - mn0);
            p[nt][1] = exp2_h2(sfr[nt][2] - mn1, sfr[nt][3] - mn1);
        }

        float al0 = ex2f(mr0 - mn0);
        float al1 = ex2f(mr1 - mn1);
        mr0 = mn0; mr1 = mn1;
        if (upd) {
#pragma unroll
            for (int nt = 0; nt < 8; nt++) {
                ofr[nt][0] *= al0; ofr[nt][1] *= al0;
                ofr[nt][2] *= al1; ofr[nt][3] *= al1;
            }
            lfr[0] *= al0; lfr[1] *= al0;
            lfr[2] *= al1; lfr[3] *= al1;
        }

#pragma unroll
        for (int kc = 0; kc < 2; kc++) {
            uint32_t pa[4] = {p[2 * kc][0], p[2 * kc][1],
                              p[2 * kc + 1][0], p[2 * kc + 1][1]};
#pragma unroll
            for (int j = 0; j < 4; j++) {
                uint32_t b0, b1, b2, b3;
                LDSM4(b0, b1, b2, b3, vb + voff[j] + kc * 32);
                mma16(ofr[2 * j],     pa, b0, b1);
                mma16(ofr[2 * j + 1], pa, b2, b3);
            }
            mma16(lfr, pa, ONES2, ONES2);
        }
    };

    for (int t3 = 0; t3 < 63; t3 += 3) {
        body(t3 + 0, 0, 2);
        body(t3 + 1, 1, 0);
        body(t3 + 2, 2, 1);
    }
    body(63, 0, 2);

    float lr0 = lfr[0], lr1 = lfr[2];

    __syncthreads();
    if (wn == 1) {
#pragma unroll
        for (int nt = 0; nt < 8; nt++) {
            *(float2*)(obuf + (m0 + g) * 66 + nt * 8 + 2 * lq) =
                make_float2(ofr[nt][0], ofr[nt][1]);
            *(float2*)(obuf + (m0 + 8 + g) * 66 + nt * 8 + 2 * lq) =
                make_float2(ofr[nt][2], ofr[nt][3]);
        }
        if (lq == 0) {
            *(float2*)(obuf + (m0 + g) * 66 + 64) = make_float2(mr0, lr0);
            *(float2*)(obuf + (m0 + 8 + g) * 66 + 64) = make_float2(mr1, lr1);
        }
    }
    __syncthreads();
    if (wn == 0) {
        float2 ml0 = *(const float2*)(obuf + (m0 + g) * 66 + 64);
        float2 ml1 = *(const float2*)(obuf + (m0 + 8 + g) * 66 + 64);
        float M0 = fmaxf(mr0, ml0.x);
        float M1 = fmaxf(mr1, ml1.x);
        float e00 = ex2f(mr0 - M0), e01 = ex2f(ml0.x - M0);
        float e10 = ex2f(mr1 - M1), e11 = ex2f(ml1.x - M1);
        float il0 = 1.f / (lr0 * e00 + ml0.y * e01);
        float il1 = 1.f / (lr1 * e10 + ml1.y * e11);
        int n0g = qt * 64 + m0 + g;
#pragma unroll
        for (int nt = 0; nt < 8; nt++) {
            float2 oa = *(const float2*)(obuf + (m0 + g) * 66 + nt * 8 + 2 * lq);
            float2 ob = *(const float2*)(obuf + (m0 + 8 + g) * 66 + nt * 8 + 2 * lq);
            int col = h * HD + nt * 8 + 2 * lq;
            *(uint32_t*)(g_Hh + (size_t)n0g * DMODEL + col) =
                packh2((ofr[nt][0] * e00 + oa.x * e01) * il0,
                       (ofr[nt][1] * e00 + oa.y * e01) * il0);
            *(uint32_t*)(g_Hh + (size_t)(n0g + 8) * DMODEL + col) =
                packh2((ofr[nt][2] * e10 + ob.x * e11) * il1,
                       (ofr[nt][3] * e10 + ob.y * e11) * il1);
        }
    }
}

// ---------------------------------------------------------------------------
extern "C" void kernel_launch(void* const* d_in, const int* in_sizes, int n_in,
                              void* d_out, int out_size) {
    const float* q  = (const float*)d_in[0];
    const float* k  = (const float*)d_in[1];
    const float* v  = (const float*)d_in[2];
    const float* Wq = (const float*)d_in[3];
    const float* Wk = (const float*)d_in[4];
    const float* Wv = (const float*)d_in[5];
    const float* Wo = (const float*)d_in[6];

    __half *Hp, *Whp;
    cudaGetSymbolAddress((void**)&Hp, g_Hh);
    cudaGetSymbolAddress((void**)&Whp, g_Wh);

    cudaFuncSetAttribute(gemm_fp16, cudaFuncAttributeMaxDynamicSharedMemorySize, G_SMEM);
    cudaFuncSetAttribute(flash_h6, cudaFuncAttributeMaxDynamicSharedMemorySize, FH_SMEM);

    cvt_all<<<dim3(2048, 1, 7), 256>>>(q, k, v, Wq, Wk, Wv, Wo);

    gemm_fp16<<<dim3(8, 32, 3), 256, G_SMEM>>>(nullptr, nullptr, nullptr, 1);

    flash_h6<<<dim3(NTOK / 64, NH), 256, FH_SMEM>>>();

    gemm_fp16<<<dim3(8, 32, 1), 256, G_SMEM>>>(
        Hp, Whp + (size_t)3 * DMODEL * DMODEL, (float*)d_out, 0);
}